// round 1
// baseline (speedup 1.0000x reference)
#include <cuda_runtime.h>
#include <math.h>

// Problem constants: x is (B, F) row-major fp32
#define B_ROWS 32768
#define F_COLS 1024
#define F4     (F_COLS / 4)          // 256 float4 per row
#define CHUNKS 256                   // row chunks for stage-1 partials
#define ROWS_PER_CHUNK (B_ROWS / CHUNKS)  // 128
#define EPS 1e-5f

// Scratch (no allocations allowed in kernel_launch)
__device__ float g_psum[CHUNKS * F_COLS];    // [chunk][col] partial sums
__device__ float g_psqr[CHUNKS * F_COLS];    // [chunk][col] partial sum of squares
__device__ float g_mean[F_COLS];
__device__ float g_rstd[F_COLS];

// ---------------------------------------------------------------------------
// Stage 1: per-(chunk, column) partial sums. Grid = CHUNKS blocks x 256 thr.
// Thread t owns 4 columns (float4 lane), loops over 128 rows of its chunk.
// Fully coalesced: 256 threads * 16B = one full 4KB row per iteration.
// ---------------------------------------------------------------------------
__global__ __launch_bounds__(256) void stage1_partials(const float* __restrict__ x) {
    const int chunk = blockIdx.x;
    const int t = threadIdx.x;                 // 0..255 -> columns 4t..4t+3
    const float4* __restrict__ x4 = reinterpret_cast<const float4*>(x);

    float4 s = make_float4(0.f, 0.f, 0.f, 0.f);
    float4 q = make_float4(0.f, 0.f, 0.f, 0.f);

    const size_t base = (size_t)chunk * ROWS_PER_CHUNK * F4 + t;
#pragma unroll 8
    for (int r = 0; r < ROWS_PER_CHUNK; ++r) {
        float4 v = __ldg(&x4[base + (size_t)r * F4]);
        s.x += v.x; s.y += v.y; s.z += v.z; s.w += v.w;
        q.x += v.x * v.x; q.y += v.y * v.y; q.z += v.z * v.z; q.w += v.w * v.w;
    }

    reinterpret_cast<float4*>(g_psum)[chunk * F4 + t] = s;
    reinterpret_cast<float4*>(g_psqr)[chunk * F4 + t] = q;
}

// ---------------------------------------------------------------------------
// Stage 2: reduce CHUNKS partials per column (deterministic fixed order),
// produce mean and rstd = 1/(sqrt(var)+eps). var = (S_in + M2)/(B-1).
// Grid = 8 blocks x 128 threads = 1024 threads, one per column.
// ---------------------------------------------------------------------------
__global__ __launch_bounds__(128) void stage2_finalize(const float* __restrict__ S_in) {
    const int f = blockIdx.x * blockDim.x + threadIdx.x;   // 0..1023
    float s = 0.f, q = 0.f;
#pragma unroll 8
    for (int c = 0; c < CHUNKS; ++c) {
        s += g_psum[c * F_COLS + f];
        q += g_psqr[c * F_COLS + f];
    }
    const float n = (float)B_ROWS;
    float mean = s / n;
    float m2 = q - n * mean * mean + S_in[f];   // exact Welford M2 adds input S
    float var = m2 / (n - 1.0f);
    g_mean[f] = mean;
    g_rstd[f] = 1.0f / (sqrtf(var) + EPS);
}

// ---------------------------------------------------------------------------
// Stage 3: normalize. One thread per float4 (8M threads). mean/rstd are 8KB
// arrays -> L1-resident after first touch per SM.
// ---------------------------------------------------------------------------
__global__ __launch_bounds__(256) void stage3_normalize(const float* __restrict__ x,
                                                        float* __restrict__ out) {
    const size_t i = (size_t)blockIdx.x * blockDim.x + threadIdx.x;   // float4 index
    const int c4 = (int)(i & (F4 - 1));                               // column group

    float4 v = __ldg(&reinterpret_cast<const float4*>(x)[i]);
    float4 m = reinterpret_cast<const float4*>(g_mean)[c4];
    float4 r = reinterpret_cast<const float4*>(g_rstd)[c4];

    float4 o;
    o.x = (v.x - m.x) * r.x;
    o.y = (v.y - m.y) * r.y;
    o.z = (v.z - m.z) * r.z;
    o.w = (v.w - m.w) * r.w;
    reinterpret_cast<float4*>(out)[i] = o;
}

extern "C" void kernel_launch(void* const* d_in, const int* in_sizes, int n_in,
                              void* d_out, int out_size) {
    const float* x    = (const float*)d_in[0];   // (32768, 1024) fp32
    // d_in[1] = M buffer (ignored: first Welford sample overwrites M)
    const float* S_in = (const float*)d_in[2];   // (1024,) fp32, added into M2
    float* out = (float*)d_out;

    stage1_partials<<<CHUNKS, 256>>>(x);
    stage2_finalize<<<F_COLS / 128, 128>>>(S_in);

    const size_t n4 = (size_t)B_ROWS * F4;       // 8M float4
    stage3_normalize<<<(unsigned)(n4 / 256), 256>>>(x, out);
}

// round 2
// speedup vs baseline: 1.1264x; 1.1264x over previous
#include <cuda_runtime.h>
#include <math.h>

// x is (B, F) row-major fp32
#define B_ROWS 32768
#define F_COLS 1024
#define F4     (F_COLS / 4)                 // 256 float4 per row
#define CHUNKS 1024                         // stage-1 row chunks (occupancy!)
#define ROWS_PER_CHUNK (B_ROWS / CHUNKS)    // 32
#define EPS 1e-5f

// Scratch (allocations forbidden)
__device__ float g_psum[CHUNKS * F_COLS];   // [chunk][col] partial sums   (4 MB)
__device__ float g_psqr[CHUNKS * F_COLS];   // [chunk][col] partial sumsq  (4 MB)
__device__ float g_mean[F_COLS];
__device__ float g_rstd[F_COLS];

// ---------------------------------------------------------------------------
// Stage 1: per-(chunk, column) partials. Grid = 1024 blocks x 256 threads
// (~7 CTAs/SM). Thread t owns 4 columns; loops 32 rows. Fully coalesced:
// a warp covers 512B of a row; block covers a full 4KB row per iteration.
// ---------------------------------------------------------------------------
__global__ __launch_bounds__(256) void stage1_partials(const float* __restrict__ x) {
    const int chunk = blockIdx.x;
    const int t = threadIdx.x;
    const float4* __restrict__ x4 = reinterpret_cast<const float4*>(x);

    float4 s = make_float4(0.f, 0.f, 0.f, 0.f);
    float4 q = make_float4(0.f, 0.f, 0.f, 0.f);

    const size_t base = (size_t)chunk * ROWS_PER_CHUNK * F4 + t;
#pragma unroll 8
    for (int r = 0; r < ROWS_PER_CHUNK; ++r) {
        float4 v = __ldg(&x4[base + (size_t)r * F4]);
        s.x += v.x; s.y += v.y; s.z += v.z; s.w += v.w;
        q.x = fmaf(v.x, v.x, q.x); q.y = fmaf(v.y, v.y, q.y);
        q.z = fmaf(v.z, v.z, q.z); q.w = fmaf(v.w, v.w, q.w);
    }

    reinterpret_cast<float4*>(g_psum)[chunk * F4 + t] = s;
    reinterpret_cast<float4*>(g_psqr)[chunk * F4 + t] = q;
}

// ---------------------------------------------------------------------------
// Stage 2: one block per column. 128 threads each read 8 chunk-partials
// (L2-resident), tree-reduce in shared memory (fixed order: deterministic),
// thread 0 writes mean and rstd = 1/(sqrt(var)+eps). var = (M2 + S_in)/(B-1).
// ---------------------------------------------------------------------------
__global__ __launch_bounds__(128) void stage2_finalize(const float* __restrict__ S_in) {
    __shared__ float sh_s[128];
    __shared__ float sh_q[128];
    const int f = blockIdx.x;        // column 0..1023
    const int t = threadIdx.x;       // 0..127

    float s = 0.f, q = 0.f;
#pragma unroll
    for (int k = 0; k < CHUNKS / 128; ++k) {
        const int c = k * 128 + t;
        s += g_psum[c * F_COLS + f];
        q += g_psqr[c * F_COLS + f];
    }
    sh_s[t] = s; sh_q[t] = q;
    __syncthreads();
#pragma unroll
    for (int w = 64; w > 0; w >>= 1) {
        if (t < w) { sh_s[t] += sh_s[t + w]; sh_q[t] += sh_q[t + w]; }
        __syncthreads();
    }
    if (t == 0) {
        const float n = (float)B_ROWS;
        float mean = sh_s[0] / n;
        float m2 = sh_q[0] - n * mean * mean + S_in[f];
        float var = m2 / (n - 1.0f);
        g_mean[f] = mean;
        g_rstd[f] = 1.0f / (sqrtf(var) + EPS);
    }
}

// ---------------------------------------------------------------------------
// Stage 3: normalize. Blocks iterate in REVERSE order so x is read back-to-
// front: the tail of x is the most-recently-touched data from stage1 and is
// still L2-resident (x = 128MB vs 126MB L2). Output stored with __stcs
// (streaming / evict-first) so the 128MB of stores don't evict x lines ahead
// of the read pointer.
// ---------------------------------------------------------------------------
__global__ __launch_bounds__(256) void stage3_normalize(const float* __restrict__ x,
                                                        float* __restrict__ out) {
    const unsigned bid = gridDim.x - 1u - blockIdx.x;              // reversed
    const size_t i = (size_t)bid * blockDim.x + threadIdx.x;       // float4 idx
    const int c4 = (int)(i & (F4 - 1));

    float4 v = __ldg(&reinterpret_cast<const float4*>(x)[i]);
    float4 m = reinterpret_cast<const float4*>(g_mean)[c4];
    float4 r = reinterpret_cast<const float4*>(g_rstd)[c4];

    float4 o;
    o.x = (v.x - m.x) * r.x;
    o.y = (v.y - m.y) * r.y;
    o.z = (v.z - m.z) * r.z;
    o.w = (v.w - m.w) * r.w;
    __stcs(&reinterpret_cast<float4*>(out)[i], o);
}

extern "C" void kernel_launch(void* const* d_in, const int* in_sizes, int n_in,
                              void* d_out, int out_size) {
    const float* x    = (const float*)d_in[0];   // (32768, 1024) fp32
    // d_in[1] = running-mean buffer M: overwritten by first Welford sample -> unused
    const float* S_in = (const float*)d_in[2];   // (1024,) running M2, added in
    float* out = (float*)d_out;

    stage1_partials<<<CHUNKS, 256>>>(x);
    stage2_finalize<<<F_COLS, 128>>>(S_in);

    const size_t n4 = (size_t)B_ROWS * F4;       // 8M float4
    stage3_normalize<<<(unsigned)(n4 / 256), 256>>>(x, out);
}

// round 3
// speedup vs baseline: 1.1909x; 1.0573x over previous
#include <cuda_runtime.h>
#include <math.h>

// x is (B, F) row-major fp32
#define B_ROWS 32768
#define F_COLS 1024
#define F4     (F_COLS / 4)                 // 256 float4 per row
#define CHUNKS 1024                         // stage-1 row chunks
#define ROWS_PER_CHUNK (B_ROWS / CHUNKS)    // 32
#define EPS 1e-5f

// Scratch (allocations forbidden)
__device__ float g_psum[CHUNKS * F_COLS];   // [chunk][col] partial sums   (4 MB)
__device__ float g_psqr[CHUNKS * F_COLS];   // [chunk][col] partial sumsq  (4 MB)
__device__ float g_mean[F_COLS];
__device__ float g_rstd[F_COLS];

// ---------------------------------------------------------------------------
// Stage 1: per-(chunk, column) partials. Thread t owns 4 columns (one float4
// lane); 32 rows per chunk processed in 4 groups of 8 EXPLICITLY BATCHED
// loads (register array) to force MLP_p1=8 in SASS. Partial stores use .cs
// (evict-first) so the 8MB scratch doesn't evict x from L2.
// ---------------------------------------------------------------------------
__global__ __launch_bounds__(256) void stage1_partials(const float* __restrict__ x) {
    const int chunk = blockIdx.x;
    const int t = threadIdx.x;
    const float4* __restrict__ x4 = reinterpret_cast<const float4*>(x);

    float4 s = make_float4(0.f, 0.f, 0.f, 0.f);
    float4 q = make_float4(0.f, 0.f, 0.f, 0.f);

    const size_t base = (size_t)chunk * ROWS_PER_CHUNK * F4 + t;

#pragma unroll
    for (int g = 0; g < ROWS_PER_CHUNK / 8; ++g) {
        float4 v[8];
#pragma unroll
        for (int j = 0; j < 8; ++j)
            v[j] = __ldg(&x4[base + (size_t)(g * 8 + j) * F4]);
#pragma unroll
        for (int j = 0; j < 8; ++j) {
            s.x += v[j].x; s.y += v[j].y; s.z += v[j].z; s.w += v[j].w;
            q.x = fmaf(v[j].x, v[j].x, q.x);
            q.y = fmaf(v[j].y, v[j].y, q.y);
            q.z = fmaf(v[j].z, v[j].z, q.z);
            q.w = fmaf(v[j].w, v[j].w, q.w);
        }
    }

    __stcs(&reinterpret_cast<float4*>(g_psum)[chunk * F4 + t], s);
    __stcs(&reinterpret_cast<float4*>(g_psqr)[chunk * F4 + t], q);
}

// ---------------------------------------------------------------------------
// Stage 2: one block per column; 128 threads read 8 chunk-partials each
// (.cs: consumed once), tree-reduce in shared memory (fixed order ->
// deterministic). var = (M2 + S_in)/(B-1); rstd = 1/(sqrt(var)+eps).
// ---------------------------------------------------------------------------
__global__ __launch_bounds__(128) void stage2_finalize(const float* __restrict__ S_in) {
    __shared__ float sh_s[128];
    __shared__ float sh_q[128];
    const int f = blockIdx.x;        // column 0..1023
    const int t = threadIdx.x;       // 0..127

    float s = 0.f, q = 0.f;
#pragma unroll
    for (int k = 0; k < CHUNKS / 128; ++k) {
        const int c = k * 128 + t;
        s += __ldcs(&g_psum[c * F_COLS + f]);
        q += __ldcs(&g_psqr[c * F_COLS + f]);
    }
    sh_s[t] = s; sh_q[t] = q;
    __syncthreads();
#pragma unroll
    for (int w = 64; w > 0; w >>= 1) {
        if (t < w) { sh_s[t] += sh_s[t + w]; sh_q[t] += sh_q[t + w]; }
        __syncthreads();
    }
    if (t == 0) {
        const float n = (float)B_ROWS;
        float mean = sh_s[0] / n;
        float m2 = sh_q[0] - n * mean * mean + S_in[f];
        float var = m2 / (n - 1.0f);
        g_mean[f] = mean;
        g_rstd[f] = 1.0f / (sqrtf(var) + EPS);
    }
}

// ---------------------------------------------------------------------------
// Stage 3: normalize. Each block handles 4 consecutive rows (1024 float4);
// thread t handles column-group t in each of the 4 rows -> one mean/rstd
// load, 4 BATCHED x loads (MLP_p1=4). Blocks run in REVERSE order (tail of x
// is L2-hot after stage1). Reads .cs (no reuse -> evict-first, protects the
// unread front of x in L2); writes .cs (streaming).
// ---------------------------------------------------------------------------
__global__ __launch_bounds__(256) void stage3_normalize(const float* __restrict__ x,
                                                        float* __restrict__ out) {
    const unsigned bid = gridDim.x - 1u - blockIdx.x;               // reversed
    const int t = threadIdx.x;                                      // == column group
    const size_t base = (size_t)bid * 1024 + t;                     // float4 index

    const float4* __restrict__ x4 = reinterpret_cast<const float4*>(x);
    float4* __restrict__ o4 = reinterpret_cast<float4*>(out);

    float4 v[4];
#pragma unroll
    for (int k = 0; k < 4; ++k)
        v[k] = __ldcs(&x4[base + (size_t)k * F4]);

    const float4 m = reinterpret_cast<const float4*>(g_mean)[t];
    const float4 r = reinterpret_cast<const float4*>(g_rstd)[t];

#pragma unroll
    for (int k = 0; k < 4; ++k) {
        float4 o;
        o.x = (v[k].x - m.x) * r.x;
        o.y = (v[k].y - m.y) * r.y;
        o.z = (v[k].z - m.z) * r.z;
        o.w = (v[k].w - m.w) * r.w;
        __stcs(&o4[base + (size_t)k * F4], o);
    }
}

extern "C" void kernel_launch(void* const* d_in, const int* in_sizes, int n_in,
                              void* d_out, int out_size) {
    const float* x    = (const float*)d_in[0];   // (32768, 1024) fp32
    // d_in[1] = running-mean buffer M: overwritten by first Welford sample -> unused
    const float* S_in = (const float*)d_in[2];   // (1024,) running M2, added in
    float* out = (float*)d_out;

    stage1_partials<<<CHUNKS, 256>>>(x);
    stage2_finalize<<<F_COLS, 128>>>(S_in);

    // 8M float4 / 1024 per block = 8192 blocks
    stage3_normalize<<<(unsigned)((size_t)B_ROWS * F4 / 1024), 256>>>(x, out);
}

// round 4
// speedup vs baseline: 1.1915x; 1.0005x over previous
#include <cuda_runtime.h>
#include <math.h>

// x is (B, F) row-major fp32
#define B_ROWS 32768
#define F_COLS 1024
#define F4     (F_COLS / 4)                 // 256 float4 per row
#define CHUNKS 1024                         // stage-1 row chunks
#define ROWS_PER_CHUNK (B_ROWS / CHUNKS)    // 32
#define EPS 1e-5f

// Scratch (allocations forbidden)
__device__ float g_psum[CHUNKS * F_COLS];   // [chunk][col] partial sums   (4 MB)
__device__ float g_psqr[CHUNKS * F_COLS];   // [chunk][col] partial sumsq  (4 MB)
__device__ float g_mean[F_COLS];
__device__ float g_rstd[F_COLS];

// ---------------------------------------------------------------------------
// Stage 1: per-(chunk, column) partials. __launch_bounds__(256, 4) grants a
// 64-reg budget so the 8 batched float4 loads (32 regs) genuinely coexist in
// flight (MLP_p1 = 8). 4 CTAs/SM x 8 warps = 32 warps/SM -> 256 outstanding
// LDG.128 per SM. Partial stores .cs so scratch doesn't evict x from L2.
// ---------------------------------------------------------------------------
__global__ __launch_bounds__(256, 4) void stage1_partials(const float* __restrict__ x) {
    const int chunk = blockIdx.x;
    const int t = threadIdx.x;
    const float4* __restrict__ x4 = reinterpret_cast<const float4*>(x);

    float4 s = make_float4(0.f, 0.f, 0.f, 0.f);
    float4 q = make_float4(0.f, 0.f, 0.f, 0.f);

    const size_t base = (size_t)chunk * ROWS_PER_CHUNK * F4 + t;

#pragma unroll
    for (int g = 0; g < ROWS_PER_CHUNK / 8; ++g) {
        float4 v[8];
#pragma unroll
        for (int j = 0; j < 8; ++j)
            v[j] = __ldg(&x4[base + (size_t)(g * 8 + j) * F4]);
#pragma unroll
        for (int j = 0; j < 8; ++j) {
            s.x += v[j].x; s.y += v[j].y; s.z += v[j].z; s.w += v[j].w;
            q.x = fmaf(v[j].x, v[j].x, q.x);
            q.y = fmaf(v[j].y, v[j].y, q.y);
            q.z = fmaf(v[j].z, v[j].z, q.z);
            q.w = fmaf(v[j].w, v[j].w, q.w);
        }
    }

    __stcs(&reinterpret_cast<float4*>(g_psum)[chunk * F4 + t], s);
    __stcs(&reinterpret_cast<float4*>(g_psqr)[chunk * F4 + t], q);
}

// ---------------------------------------------------------------------------
// Stage 2: one block per column; 128 threads read 8 chunk-partials each
// (.cs: consumed once), tree-reduce in shared memory (fixed order ->
// deterministic). var = (M2 + S_in)/(B-1); rstd = 1/(sqrt(var)+eps).
// ---------------------------------------------------------------------------
__global__ __launch_bounds__(128) void stage2_finalize(const float* __restrict__ S_in) {
    __shared__ float sh_s[128];
    __shared__ float sh_q[128];
    const int f = blockIdx.x;        // column 0..1023
    const int t = threadIdx.x;       // 0..127

    float s = 0.f, q = 0.f;
#pragma unroll
    for (int k = 0; k < CHUNKS / 128; ++k) {
        const int c = k * 128 + t;
        s += __ldcs(&g_psum[c * F_COLS + f]);
        q += __ldcs(&g_psqr[c * F_COLS + f]);
    }
    sh_s[t] = s; sh_q[t] = q;
    __syncthreads();
#pragma unroll
    for (int w = 64; w > 0; w >>= 1) {
        if (t < w) { sh_s[t] += sh_s[t + w]; sh_q[t] += sh_q[t + w]; }
        __syncthreads();
    }
    if (t == 0) {
        const float n = (float)B_ROWS;
        float mean = sh_s[0] / n;
        float m2 = sh_q[0] - n * mean * mean + S_in[f];
        float var = m2 / (n - 1.0f);
        g_mean[f] = mean;
        g_rstd[f] = 1.0f / (sqrtf(var) + EPS);
    }
}

// ---------------------------------------------------------------------------
// Stage 3: normalize. Each block handles 8 consecutive rows (2048 float4);
// thread t owns column-group t across all 8 rows -> one mean/rstd load,
// 8 BATCHED x loads (MLP_p1=8, 64-reg budget). Blocks in REVERSE order (tail
// of x is L2-hot after stage1). Reads .cs (consumed once, protects the unread
// front of x in L2); writes .cs (streaming).
// ---------------------------------------------------------------------------
__global__ __launch_bounds__(256, 4) void stage3_normalize(const float* __restrict__ x,
                                                           float* __restrict__ out) {
    const unsigned bid = gridDim.x - 1u - blockIdx.x;               // reversed
    const int t = threadIdx.x;                                      // column group
    const size_t base = (size_t)bid * (8 * F4) + t;                 // float4 index

    const float4* __restrict__ x4 = reinterpret_cast<const float4*>(x);
    float4* __restrict__ o4 = reinterpret_cast<float4*>(out);

    float4 v[8];
#pragma unroll
    for (int k = 0; k < 8; ++k)
        v[k] = __ldcs(&x4[base + (size_t)k * F4]);

    const float4 m = reinterpret_cast<const float4*>(g_mean)[t];
    const float4 r = reinterpret_cast<const float4*>(g_rstd)[t];

#pragma unroll
    for (int k = 0; k < 8; ++k) {
        float4 o;
        o.x = (v[k].x - m.x) * r.x;
        o.y = (v[k].y - m.y) * r.y;
        o.z = (v[k].z - m.z) * r.z;
        o.w = (v[k].w - m.w) * r.w;
        __stcs(&o4[base + (size_t)k * F4], o);
    }
}

extern "C" void kernel_launch(void* const* d_in, const int* in_sizes, int n_in,
                              void* d_out, int out_size) {
    const float* x    = (const float*)d_in[0];   // (32768, 1024) fp32
    // d_in[1] = running-mean buffer M: overwritten by first Welford sample -> unused
    const float* S_in = (const float*)d_in[2];   // (1024,) running M2, added in
    float* out = (float*)d_out;

    stage1_partials<<<CHUNKS, 256>>>(x);
    stage2_finalize<<<F_COLS, 128>>>(S_in);

    // 8M float4 / 2048 per block = 4096 blocks
    stage3_normalize<<<(unsigned)((size_t)B_ROWS * F4 / 2048), 256>>>(x, out);
}